// round 13
// baseline (speedup 1.0000x reference)
#include <cuda_runtime.h>
#include <cuda_bf16.h>
#include <cstdint>
#include <math.h>

#define Bc 64
#define Tc 512
#define Ec 512
#define Hc 512
#define Gc 1536            // 3*H
#define M_TOK (Bc*Tc)      // 32768 tokens
#define HY_OFF ((size_t)Bc*Tc*2*Hc)
#define NQPROD 8           // blocks per quarter barrier

// ---------------- device scratch ----------------
// gx layout: [dir][t][bhalf][jc(32)][g(3)][b_local(32)][jl(16)]
__device__ float g_gx[(size_t)2*M_TOK*Gc];
__device__ float g_h0out[(size_t)M_TOK*2*Hc];    // layer0 output [b][t][2H]

// h state bf16 hi/lo, layout [buf][(dir*4+kq)*64 + b][128] with XOR-8unit swizzle
__device__ __nv_bfloat16 g_hAhi[2][2*4*64*128];
__device__ __nv_bfloat16 g_hAlo[2][2*4*64*128];

// bf16 split operands for gx GEMMs
__device__ __nv_bfloat16 g_xs_hi[(size_t)M_TOK*Ec],  g_xs_lo[(size_t)M_TOK*Ec];
__device__ __nv_bfloat16 g_h0_hi[(size_t)M_TOK*2*Hc], g_h0_lo[(size_t)M_TOK*2*Hc];
__device__ __nv_bfloat16 g_w0_hi[(size_t)2*Gc*Ec],   g_w0_lo[(size_t)2*Gc*Ec];
__device__ __nv_bfloat16 g_w1_hi[(size_t)2*Gc*2*Hc], g_w1_lo[(size_t)2*Gc*2*Hc];

// quarter-barrier state: [group(4)][quarter(4)], padded lines
__device__ int g_bar_cnt[4 * 4 * 32];
__device__ volatile int g_bar_gen2[4 * 4 * 32];

// warp-mma helpers (base PTX)
#define LDSM4(r0, r1, r2, r3, addr) \
    asm volatile("ldmatrix.sync.aligned.m8n8.x4.shared.b16 {%0,%1,%2,%3}, [%4];" \
                 : "=r"(r0), "=r"(r1), "=r"(r2), "=r"(r3) : "r"(addr))

#define LDSM2(r0, r1, addr) \
    asm volatile("ldmatrix.sync.aligned.m8n8.x2.shared.b16 {%0,%1}, [%2];" \
                 : "=r"(r0), "=r"(r1) : "r"(addr))

#define MMA16816(d, a, b0, b1) \
    asm volatile("mma.sync.aligned.m16n8k16.row.col.f32.bf16.bf16.f32 " \
                 "{%0,%1,%2,%3}, {%4,%5,%6,%7}, {%8,%9}, {%0,%1,%2,%3};" \
                 : "+f"(d[0]), "+f"(d[1]), "+f"(d[2]), "+f"(d[3]) \
                 : "r"(a[0]), "r"(a[1]), "r"(a[2]), "r"(a[3]), "r"(b0), "r"(b1))

// bulk async copy (sm_90 base) + mbarrier
#define BULK_G2S(dst, src, bytes, mbar) \
    asm volatile("cp.async.bulk.shared::cluster.global.mbarrier::complete_tx::bytes " \
                 "[%0], [%1], %2, [%3];" \
                 :: "r"(dst), "l"(src), "r"(bytes), "r"(mbar) : "memory")
#define MBAR_INIT(mbar, cnt) \
    asm volatile("mbarrier.init.shared.b64 [%0], %1;" :: "r"(mbar), "r"(cnt) : "memory")
#define MBAR_INVAL(mbar) \
    asm volatile("mbarrier.inval.shared.b64 [%0];" :: "r"(mbar) : "memory")
#define MBAR_EXPECT(mbar, bytes) \
    asm volatile("mbarrier.arrive.expect_tx.shared.b64 _, [%0], %1;" \
                 :: "r"(mbar), "r"(bytes) : "memory")
#define MBAR_WAIT(mbar, par) do { \
    asm volatile("{\n\t.reg .pred P;\n\tW%=:\n\t" \
        "mbarrier.try_wait.parity.acquire.cta.shared::cta.b64 P, [%0], %1, 0x989680;\n\t" \
        "@!P bra W%=;\n\t}" :: "r"(mbar), "r"(par) : "memory"); \
} while (0)

#define CP_ASYNC16(saddr, gptr) \
    asm volatile("cp.async.cg.shared.global [%0], [%1], 16;" \
                 :: "r"(saddr), "l"(gptr) : "memory")
#define CP_COMMIT() asm volatile("cp.async.commit_group;" ::: "memory")
#define CP_WAIT1()  asm volatile("cp.async.wait_group 1;" ::: "memory")
#define CP_WAIT0()  asm volatile("cp.async.wait_group 0;" ::: "memory")

__device__ __forceinline__ uint32_t smem_u32(const void* p) {
    uint32_t a;
    asm("{ .reg .u64 t; cvta.to.shared.u64 t, %1; cvt.u32.u64 %0, t; }" : "=r"(a) : "l"(p));
    return a;
}

// ---------------- bf16 split prep ----------------
__global__ void split_bf16_kernel(const float* __restrict__ src,
                                  __nv_bfloat16* __restrict__ hi,
                                  __nv_bfloat16* __restrict__ lo, size_t n) {
    size_t i = (size_t)blockIdx.x * blockDim.x + threadIdx.x;
    if (i >= n) return;
    float a = src[i];
    __nv_bfloat16 h = __float2bfloat16(a);
    hi[i] = h;
    lo[i] = __float2bfloat16(a - __bfloat162float(h));
}

// ---------------- zero hidden state (buf 0, both splits) ----------------
__global__ void zero_h_kernel() {
    int i = blockIdx.x * blockDim.x + threadIdx.x;   // 65536
    g_hAhi[0][i] = __float2bfloat16(0.0f);
    g_hAlo[0][i] = __float2bfloat16(0.0f);
}

// ---------------- tensor-core gx GEMM: cp.async double-buffered ------------
#define KC 32
#define PITCH 40
#define TILE_B (128 * PITCH * 2)      // 10240 bytes per tile
#define GEMM_SMEM (2 * 4 * TILE_B)    // 81920 bytes

__global__ void __launch_bounds__(256, 2)
gemm_mma(const __nv_bfloat16* __restrict__ Ahi, const __nv_bfloat16* __restrict__ Alo,
         const __nv_bfloat16* __restrict__ Whi, const __nv_bfloat16* __restrict__ Wlo,
         const float* __restrict__ bias, int K)
{
    extern __shared__ char gsm[];
    uint32_t base = smem_u32(gsm);

    int tid  = threadIdx.x;
    int wid  = tid >> 5, lane = tid & 31;
    int dir  = blockIdx.z;
    int n0   = blockIdx.x * 128;
    int m0   = blockIdx.y * 128;
    int wm   = wid >> 1;
    int wn   = wid & 1;

    const __nv_bfloat16* bhi = Whi + (size_t)dir * Gc * K;
    const __nv_bfloat16* blo = Wlo + (size_t)dir * Gc * K;
    float* C = g_gx + (size_t)dir * M_TOK * Gc;
    const float* bp = bias + dir * Gc;

    float acc[2][8][4];
#pragma unroll
    for (int i = 0; i < 2; i++)
#pragma unroll
        for (int j = 0; j < 8; j++)
#pragma unroll
            for (int q = 0; q < 4; q++) acc[i][j][q] = 0.0f;

    int a_row = (lane & 15);
    int a_col = (lane >> 4) * 8;
    int b_row = (lane & 7) + ((lane >> 4) & 1) * 8;
    int b_col = ((lane >> 3) & 1) * 8;

    // staging per thread: 8 granules of 16B across 4 tiles
    int s_tile = 0;   // computed per granule
    const int nchunks = K / KC;

    // stage chunk c into buffer buf
    auto stage = [&](int c, int buf) {
        int k0 = c * KC;
#pragma unroll
        for (int p = 0; p < 8; p++) {
            int idx = p * 256 + tid;          // 0..2047
            int tile = idx >> 9;              // 0..3
            int g2   = idx & 511;
            int r    = g2 >> 2;
            int c4   = g2 & 3;
            const __nv_bfloat16* src;
            if (tile == 0)      src = Ahi + (size_t)(m0 + r) * K + k0 + c4 * 8;
            else if (tile == 1) src = Alo + (size_t)(m0 + r) * K + k0 + c4 * 8;
            else if (tile == 2) src = bhi + (size_t)(n0 + r) * K + k0 + c4 * 8;
            else                src = blo + (size_t)(n0 + r) * K + k0 + c4 * 8;
            uint32_t dst = base + (uint32_t)((buf * 4 + tile) * TILE_B)
                         + (uint32_t)((r * PITCH + c4 * 8) * 2);
            CP_ASYNC16(dst, (const void*)src);
        }
        CP_COMMIT();
    };
    (void)s_tile;

    stage(0, 0);
    for (int c = 0; c < nchunks; c++) {
        if (c + 1 < nchunks) { stage(c + 1, (c + 1) & 1); CP_WAIT1(); }
        else                 { CP_WAIT0(); }
        __syncthreads();

        uint32_t bb = base + (uint32_t)((c & 1) * 4 * TILE_B);
        uint32_t uAhi = bb, uAlo = bb + TILE_B, uBhi = bb + 2 * TILE_B, uBlo = bb + 3 * TILE_B;

#pragma unroll
        for (int kk = 0; kk < 2; kk++) {
            int k16 = kk * 16;
            uint32_t ahi[2][4], alo[2][4];
#pragma unroll
            for (int mt = 0; mt < 2; mt++) {
                uint32_t off = 2u * ((wm * 32 + mt * 16 + a_row) * PITCH + k16 + a_col);
                LDSM4(ahi[mt][0], ahi[mt][1], ahi[mt][2], ahi[mt][3], uAhi + off);
                LDSM4(alo[mt][0], alo[mt][1], alo[mt][2], alo[mt][3], uAlo + off);
            }
#pragma unroll
            for (int np = 0; np < 4; np++) {
                uint32_t off = 2u * ((wn * 64 + np * 16 + b_row) * PITCH + k16 + b_col);
                uint32_t bh0, bh1, bh2, bh3, bl0, bl1, bl2, bl3;
                LDSM4(bh0, bh1, bh2, bh3, uBhi + off);
                LDSM4(bl0, bl1, bl2, bl3, uBlo + off);
#pragma unroll
                for (int mt = 0; mt < 2; mt++) {
                    MMA16816(acc[mt][np * 2 + 0], ahi[mt], bh0, bh1);
                    MMA16816(acc[mt][np * 2 + 0], ahi[mt], bl0, bl1);
                    MMA16816(acc[mt][np * 2 + 0], alo[mt], bh0, bh1);
                    MMA16816(acc[mt][np * 2 + 1], ahi[mt], bh2, bh3);
                    MMA16816(acc[mt][np * 2 + 1], ahi[mt], bl2, bl3);
                    MMA16816(acc[mt][np * 2 + 1], alo[mt], bh2, bh3);
                }
            }
        }
        __syncthreads();
    }

    // epilogue: write recurrence-friendly gx layout
#pragma unroll
    for (int mt = 0; mt < 2; mt++) {
#pragma unroll
        for (int nt = 0; nt < 8; nt++) {
            int row = m0 + wm * 32 + mt * 16 + (lane >> 2);
            int col = n0 + wn * 64 + nt * 8 + (lane & 3) * 2;
            float b0 = bp[col], b1 = bp[col + 1];
            int g = col >> 9, j = col & 511;
            int jc = j >> 4, jl = j & 15;
#pragma unroll
            for (int half = 0; half < 2; half++) {
                int r = row + half * 8;
                int bb2 = r >> 9, tt = r & 511;
                size_t addr = (size_t)tt * 98304 + (size_t)(bb2 >> 5) * 49152
                            + jc * 1536 + g * 512 + (bb2 & 31) * 16 + jl;
                float2 v = half ? make_float2(acc[mt][nt][2] + b0, acc[mt][nt][3] + b1)
                                : make_float2(acc[mt][nt][0] + b0, acc[mt][nt][1] + b1);
                *(float2*)&C[addr] = v;
            }
        }
    }
}

// ---------------- persistent MMA recurrence (quarter-K barriers) -----------
#define RPITCH 520
#define PG 41
#define OFF_WHI 0
#define SZ_W    (48 * RPITCH * 2)               // 49920
#define OFF_WLO (OFF_WHI + SZ_W)
#define OFF_HHI (OFF_WLO + SZ_W)                // [kq(4)][32][128] swizzled
#define SZ_H    (4 * 32 * 128 * 2)              // 32768
#define OFF_HLO (OFF_HHI + SZ_H)
#define OFF_G   (OFF_HLO + SZ_H)                // [48][41] floats (K-half 0)
#define OFF_G2  (OFF_G + 48 * PG * 4)           // [48][41] floats (K-half 1)
#define OFF_GX  (OFF_G2 + 48 * PG * 4)          // [2][1536] floats
#define OFF_X   (OFF_GX + 12288)                // [32][16] floats
#define OFF_MB  (OFF_X + 2048)                  // 6 mbarriers
#define PERSIST_SMEM (OFF_MB + 64)

__global__ void __launch_bounds__(256, 1)
gru_persist_mma(const float* __restrict__ w_hh,
                const float* __restrict__ b_hh,
                float* __restrict__ out_l1,
                int layer)
{
    extern __shared__ char sm[];
    __nv_bfloat16* sWhi = (__nv_bfloat16*)(sm + OFF_WHI);
    __nv_bfloat16* sWlo = (__nv_bfloat16*)(sm + OFF_WLO);
    __nv_bfloat16* sHhi = (__nv_bfloat16*)(sm + OFF_HHI);
    __nv_bfloat16* sHlo = (__nv_bfloat16*)(sm + OFF_HLO);
    float* sG  = (float*)(sm + OFF_G);
    float* sG2 = (float*)(sm + OFF_G2);
    float* sGX = (float*)(sm + OFF_GX);
    float* sX  = (float*)(sm + OFF_X);

    int tid = threadIdx.x, lane = tid & 31, wid = tid >> 5;
    int dir   = blockIdx.z;
    int bhalf = blockIdx.y;
    int j0    = blockIdx.x * 16;
    int b0    = bhalf * 32;
    int grp   = dir * 2 + bhalf;
    int myq   = blockIdx.x >> 3;           // producer quarter (0..3)
    int imine = (grp * 4 + myq) * 32;

    // replay-safe generation bases for all 4 quarters
    int gbase_q[4];
#pragma unroll
    for (int q = 0; q < 4; q++) gbase_q[q] = g_bar_gen2[(grp * 4 + q) * 32];
    int gbase_mine = gbase_q[myq];

    uint32_t sbase = smem_u32(sm);
    uint32_t mb_q[4];
#pragma unroll
    for (int q = 0; q < 4; q++) mb_q[q] = sbase + OFF_MB + q * 8;
    uint32_t mb_g0 = sbase + OFF_MB + 32;
    uint32_t mb_g1 = sbase + OFF_MB + 40;

    // split-K warp mapping: warps 0-3 -> quarters 0,1; warps 4-7 -> quarters 2,3
    int wlocal  = wid & 3;
    int khalf_w = wid >> 2;
    int wm  = wlocal & 1;
    int wn2 = wlocal >> 1;
    int nbase = wn2 * 24;
    int m_base = wm * 16;
    float* sGmine = khalf_w ? sG2 : sG;

    int jl = tid & 15;
    int lbase = tid >> 4;
    int jglob = j0 + jl;

    int lb2 = tid >> 3;          // writer batch 0..31
    int jp  = (tid & 7) * 2;     // writer j-pair

    // one-time: load + split W slice (48 rows, gate-major r = g*16 + jj)
    const float* W = w_hh + (size_t)dir * Gc * Hc;
    for (int idx = tid; idx < 48 * 512; idx += 256) {
        int r = idx >> 9, k = idx & 511;
        int gg = r >> 4, jj = r & 15;
        float w = W[(size_t)(gg * Hc + j0 + jj) * Hc + k];
        __nv_bfloat16 h = __float2bfloat16(w);
        sWhi[r * RPITCH + k] = h;
        sWlo[r * RPITCH + k] = __float2bfloat16(w - __bfloat162float(h));
    }
    float br = __ldg(&b_hh[dir * Gc + jglob]);
    float bz = __ldg(&b_hh[dir * Gc + Hc + jglob]);
    float bn = __ldg(&b_hh[dir * Gc + 2 * Hc + jglob]);

    const float* gxblk = g_gx + (size_t)dir * M_TOK * Gc
                       + (size_t)bhalf * 49152 + (size_t)blockIdx.x * 1536;
    float* hs = (layer == 0) ? g_h0out : out_l1;

    uint32_t uWhi = smem_u32(sWhi), uWlo = smem_u32(sWlo);
    uint32_t uHhi = smem_u32(sHhi), uHlo = smem_u32(sHlo);
    uint32_t uGX  = smem_u32(sGX);

    int a_row = lane & 15, a_col = (lane >> 4) * 8;
    int b_row = (lane & 7) + ((lane >> 4) & 1) * 8, b_col = ((lane >> 3) & 1) * 8;
    int b_row2 = 16 + (lane & 7);

    // writer constants (swizzled global h layout, quarter-granular)
    int wq    = j0 >> 7;
    int wjloc = (j0 & 127) + jp;
    int wunit = (wjloc >> 3) ^ (lb2 & 7);
    int woff  = ((dir * 4 + wq) * 64 + (b0 + lb2)) * 128 + (wunit << 3) + (wjloc & 7);
    // hp reader constants
    int hq    = jglob >> 7;
    int hjloc = jglob & 127;

    if (tid == 0) {
#pragma unroll
        for (int q = 0; q < 4; q++) MBAR_INIT(mb_q[q], 1);
        MBAR_INIT(mb_g0, 1); MBAR_INIT(mb_g1, 1);
    }
    __syncthreads();

    // prologue: gx(0) bulk into buf 0
    if (tid == 0) {
        int t0 = dir ? (Tc - 1) : 0;
        MBAR_EXPECT(mb_g0, 6144u);
        BULK_G2S(uGX, (const void*)(gxblk + (size_t)t0 * 98304), 6144u, mb_g0);
    }
    int gxph0 = 0, gxph1 = 0;

    for (int s = 0; s < Tc; s++) {
        int rbuf = s & 1;
        int par = s & 1;
        int t = dir ? (Tc - 1 - s) : s;
        const __nv_bfloat16* hAhi = g_hAhi[rbuf];
        const __nv_bfloat16* hAlo = g_hAlo[rbuf];
        __nv_bfloat16* wAhi = g_hAhi[rbuf ^ 1];
        __nv_bfloat16* wAlo = g_hAlo[rbuf ^ 1];

        // tid0: per-quarter poll -> issue bulks (pipelines with MMA waits below)
        if (tid == 0) {
#pragma unroll
            for (int q = 0; q < 4; q++) {
                if (s > 0) while (g_bar_gen2[(grp * 4 + q) * 32] - gbase_q[q] < s) { }
                size_t src = (size_t)((dir * 4 + q) * 64 + b0) * 128;
                MBAR_EXPECT(mb_q[q], 16384u);
                BULK_G2S(uHhi + q * 8192, (const void*)(hAhi + src), 8192u, mb_q[q]);
                BULK_G2S(uHlo + q * 8192, (const void*)(hAlo + src), 8192u, mb_q[q]);
            }
        }

        float acc[3][4];
#pragma unroll
        for (int i = 0; i < 3; i++)
#pragma unroll
            for (int q = 0; q < 4; q++) acc[i][q] = 0.0f;

        // ---- split-K MMA over two quarters per warp group ----
#pragma unroll
        for (int qq = 0; qq < 2; qq++) {
            int q = khalf_w * 2 + qq;
            MBAR_WAIT(mb_q[q], par);
#pragma unroll
            for (int kk = 0; kk < 8; kk++) {
                int k16 = q * 8 + kk;
                int lc = kk * 2 + (a_col >> 3);        // local 8-unit chunk 0..15
                int rowA = m_base + a_row;
                uint32_t offA = (uint32_t)(q * 8192 + rowA * 256 + ((lc ^ (rowA & 7)) << 4));
                uint32_t ahi[4], alo[4];
                LDSM4(ahi[0], ahi[1], ahi[2], ahi[3], uHhi + offA);
                LDSM4(alo[0], alo[1], alo[2], alo[3], uHlo + offA);

                uint32_t offB = (uint32_t)(((nbase + b_row) * RPITCH + k16 * 16 + b_col) * 2);
                uint32_t bh0, bh1, bh2, bh3, bl0, bl1, bl2, bl3;
                LDSM4(bh0, bh1, bh2, bh3, uWhi + offB);
                LDSM4(bl0, bl1, bl2, bl3, uWlo + offB);
                MMA16816(acc[0], ahi, bh0, bh1);
                MMA16816(acc[0], ahi, bl0, bl1);
                MMA16816(acc[0], alo, bh0, bh1);
                MMA16816(acc[1], ahi, bh2, bh3);
                MMA16816(acc[1], ahi, bl2, bl3);
                MMA16816(acc[1], alo, bh2, bh3);

                uint32_t offB2 = (uint32_t)(((nbase + b_row2) * RPITCH + k16 * 16 + b_col) * 2);
                uint32_t ch0, ch1, cl0, cl1;
                LDSM2(ch0, ch1, uWhi + offB2);
                LDSM2(cl0, cl1, uWlo + offB2);
                MMA16816(acc[2], ahi, ch0, ch1);
                MMA16816(acc[2], ahi, cl0, cl1);
                MMA16816(acc[2], alo, ch0, ch1);
            }
        }
        // dump partial gh to own buffer [gate row][batch row]
#pragma unroll
        for (int nt = 0; nt < 3; nt++) {
            int c0 = nbase + nt * 8 + (lane & 3) * 2;
            int r0 = m_base + (lane >> 2);
            sGmine[c0 * PG + r0]           = acc[nt][0];
            sGmine[(c0 + 1) * PG + r0]     = acc[nt][1];
            sGmine[c0 * PG + r0 + 8]       = acc[nt][2];
            sGmine[(c0 + 1) * PG + r0 + 8] = acc[nt][3];
        }
        __syncthreads();

        // gx ready for this step?
        if (rbuf == 0) { MBAR_WAIT(mb_g0, gxph0); gxph0 ^= 1; }
        else           { MBAR_WAIT(mb_g1, gxph1); gxph1 ^= 1; }

        // gate math (partials from both K halves)
        const float* gxs = sGX + rbuf * 1536;
#pragma unroll
        for (int rep = 0; rep < 2; rep++) {
            int lb = lbase + rep * 16;
            float ghr = sG[jl * PG + lb]        + sG2[jl * PG + lb];
            float ghz = sG[(16 + jl) * PG + lb] + sG2[(16 + jl) * PG + lb];
            float ghn = sG[(32 + jl) * PG + lb] + sG2[(32 + jl) * PG + lb];
            float gr = gxs[lb * 16 + jl];
            float gz = gxs[512 + lb * 16 + jl];
            float gn = gxs[1024 + lb * 16 + jl];
            int hidx = hq * 4096 + lb * 128 + (((hjloc >> 3) ^ (lb & 7)) << 3) + (hjloc & 7);
            float hp = __bfloat162float(sHhi[hidx]) + __bfloat162float(sHlo[hidx]);
            float rr = 1.0f / (1.0f + __expf(-(gr + ghr + br)));
            float zz = 1.0f / (1.0f + __expf(-(gz + ghz + bz)));
            float xa = gn + rr * (ghn + bn);
            float e2 = __expf(2.0f * xa);
            float nn = 1.0f - __fdividef(2.0f, e2 + 1.0f);
            sX[lb * 16 + jl] = (1.0f - zz) * nn + zz * hp;
        }
        __syncthreads();

        // h_new global write (swizzled layout): one bf16x2 per array per thread
        {
            float v0 = sX[lb2 * 16 + jp];
            float v1 = sX[lb2 * 16 + jp + 1];
            __nv_bfloat16 h0 = __float2bfloat16(v0), h1 = __float2bfloat16(v1);
            __nv_bfloat162 hi01 = {h0, h1};
            __nv_bfloat162 lo01 = {__float2bfloat16(v0 - __bfloat162float(h0)),
                                   __float2bfloat16(v1 - __bfloat162float(h1))};
            *(__nv_bfloat162*)(wAhi + woff) = hi01;
            *(__nv_bfloat162*)(wAlo + woff) = lo01;
        }
        __syncthreads();

        // arrive at own quarter barrier (skip on last step)
        if (s != Tc - 1 && tid == 0) {
            __threadfence();
            asm volatile("fence.proxy.async;" ::: "memory");
            int old = atomicAdd(&g_bar_cnt[imine], 1);
            if (old == NQPROD - 1) {
                g_bar_cnt[imine] = 0;
                __threadfence();
                g_bar_gen2[imine] = gbase_mine + s + 1;
            }
        }

        // off-critical-path: hs output (coalesced)
        {
            float2 xv = make_float2(sX[lb2 * 16 + jp], sX[lb2 * 16 + jp + 1]);
            *(float2*)&hs[((size_t)(b0 + lb2) * Tc + t) * (2 * Hc) + dir * Hc + j0 + jp] = xv;
        }
        // gx bulk prefetch for s+1
        if (s != Tc - 1 && tid == 0) {
            int tn = dir ? (Tc - 2 - s) : (s + 1);
            uint32_t mb = ((s + 1) & 1) ? mb_g1 : mb_g0;
            MBAR_EXPECT(mb, 6144u);
            BULK_G2S(uGX + ((s + 1) & 1) * 6144,
                     (const void*)(gxblk + (size_t)tn * 98304), 6144u, mb);
        }
    }

    __syncthreads();
    if (tid == 0) {
#pragma unroll
        for (int q = 0; q < 4; q++) MBAR_INVAL(mb_q[q]);
        MBAR_INVAL(mb_g0); MBAR_INVAL(mb_g1);
    }
}

// ---------------- copy final hidden states (de-swizzle) ----------------
__global__ void hy_copy_kernel(float* __restrict__ d_out, int layer) {
    int i = blockIdx.x * blockDim.x + threadIdx.x;   // 0..65535
    int dir = i >> 15;
    int rem = i & 32767;                              // = b*512 + j
    int b = rem >> 9;
    int j = rem & 511;
    int q = j >> 7, jloc = j & 127;
    int off = ((dir * 4 + q) * 64 + b) * 128 + ((((jloc >> 3) ^ (b & 7))) << 3) + (jloc & 7);
    d_out[HY_OFF + (size_t)(2 * layer + dir) * Bc * Hc + rem] =
        __bfloat162float(g_hAhi[0][off]) + __bfloat162float(g_hAlo[0][off]);
}

// ---------------- launch ----------------
extern "C" void kernel_launch(void* const* d_in, const int* in_sizes, int n_in,
                              void* d_out, int out_size)
{
    const float* xs    = (const float*)d_in[0];
    const float* w_ih0 = (const float*)d_in[1];
    const float* w_hh0 = (const float*)d_in[2];
    const float* b_ih0 = (const float*)d_in[3];
    const float* b_hh0 = (const float*)d_in[4];
    const float* w_ih1 = (const float*)d_in[5];
    const float* w_hh1 = (const float*)d_in[6];
    const float* b_ih1 = (const float*)d_in[7];
    const float* b_hh1 = (const float*)d_in[8];
    float* out = (float*)d_out;

    cudaFuncSetAttribute(gru_persist_mma,
                         cudaFuncAttributeMaxDynamicSharedMemorySize, PERSIST_SMEM);
    cudaFuncSetAttribute(gemm_mma,
                         cudaFuncAttributeMaxDynamicSharedMemorySize, GEMM_SMEM);

    __nv_bfloat16 *xs_hi, *xs_lo, *h0_hi, *h0_lo, *w0_hi, *w0_lo, *w1_hi, *w1_lo;
    cudaGetSymbolAddress((void**)&xs_hi, g_xs_hi);
    cudaGetSymbolAddress((void**)&xs_lo, g_xs_lo);
    cudaGetSymbolAddress((void**)&h0_hi, g_h0_hi);
    cudaGetSymbolAddress((void**)&h0_lo, g_h0_lo);
    cudaGetSymbolAddress((void**)&w0_hi, g_w0_hi);
    cudaGetSymbolAddress((void**)&w0_lo, g_w0_lo);
    cudaGetSymbolAddress((void**)&w1_hi, g_w1_hi);
    cudaGetSymbolAddress((void**)&w1_lo, g_w1_lo);
    float* h0out;
    cudaGetSymbolAddress((void**)&h0out, g_h0out);

    dim3 gemm_grid(Gc / 128, M_TOK / 128, 2);   // (12, 256, 2)
    dim3 persist_grid(32, 2, 2);                // 128 blocks

    size_t n_w0 = (size_t)2 * Gc * Ec;
    size_t n_w1 = (size_t)2 * Gc * 2 * Hc;
    size_t n_xs = (size_t)M_TOK * Ec;
    size_t n_h0 = (size_t)M_TOK * 2 * Hc;

    split_bf16_kernel<<<(unsigned)((n_w0 + 255) / 256), 256>>>(w_ih0, w0_hi, w0_lo, n_w0);
    split_bf16_kernel<<<(unsigned)((n_w1 + 255) / 256), 256>>>(w_ih1, w1_hi, w1_lo, n_w1);
    split_bf16_kernel<<<(unsigned)((n_xs + 255) / 256), 256>>>(xs, xs_hi, xs_lo, n_xs);

    // ---- layer 0 ----
    gemm_mma<<<gemm_grid, 256, GEMM_SMEM>>>(xs_hi, xs_lo, w0_hi, w0_lo, b_ih0, Ec);
    zero_h_kernel<<<(2 * 4 * Bc * 128) / 256, 256>>>();
    gru_persist_mma<<<persist_grid, 256, PERSIST_SMEM>>>(w_hh0, b_hh0, out, 0);
    hy_copy_kernel<<<(2 * Bc * Hc) / 256, 256>>>(out, 0);

    // ---- layer 1 ----
    split_bf16_kernel<<<(unsigned)((n_h0 + 255) / 256), 256>>>(h0out, h0_hi, h0_lo, n_h0);
    gemm_mma<<<gemm_grid, 256, GEMM_SMEM>>>(h0_hi, h0_lo, w1_hi, w1_lo, b_ih1, 2 * Hc);
    zero_h_kernel<<<(2 * 4 * Bc * 128) / 256, 256>>>();
    gru_persist_mma<<<persist_grid, 256, PERSIST_SMEM>>>(w_hh1, b_hh1, out, 1);
    hy_copy_kernel<<<(2 * Bc * Hc) / 256, 256>>>(out, 1);
}

// round 14
// speedup vs baseline: 1.1567x; 1.1567x over previous
#include <cuda_runtime.h>
#include <cuda_bf16.h>
#include <cuda_fp16.h>
#include <cstdint>
#include <math.h>

#define Bc 64
#define Tc 512
#define Ec 512
#define Hc 512
#define Gc 1536            // 3*H
#define M_TOK (Bc*Tc)      // 32768 tokens
#define HY_OFF ((size_t)Bc*Tc*2*Hc)
#define NHALF 16           // blocks per sub-barrier half

// ---------------- device scratch ----------------
// gx layout: [dir][t][bhalf][jc(32)][g(3)][b_local(32)][jl(16)]
__device__ float g_gx[(size_t)2*M_TOK*Gc];
__device__ float g_h0out[(size_t)M_TOK*2*Hc];    // layer0 output [b][t][2H]

// h state fp16 hi/lo, layout [buf][(dir*2+jhalf)*64 + b][256] with XOR-16B swizzle
__device__ __half g_hAhi[2][2*2*64*256];
__device__ __half g_hAlo[2][2*2*64*256];

// bf16 split operands for gx GEMMs
__device__ __nv_bfloat16 g_xs_hi[(size_t)M_TOK*Ec],  g_xs_lo[(size_t)M_TOK*Ec];
__device__ __nv_bfloat16 g_h0_hi[(size_t)M_TOK*2*Hc], g_h0_lo[(size_t)M_TOK*2*Hc];
__device__ __nv_bfloat16 g_w0_hi[(size_t)2*Gc*Ec],   g_w0_lo[(size_t)2*Gc*Ec];
__device__ __nv_bfloat16 g_w1_hi[(size_t)2*Gc*2*Hc], g_w1_lo[(size_t)2*Gc*2*Hc];

// sub-barrier state: [group(4)][half(2)], padded lines
__device__ int g_bar_cnt[4 * 2 * 32];
__device__ volatile int g_bar_gen2[4 * 2 * 32];

// warp-mma helpers (base PTX)
#define LDSM4(r0, r1, r2, r3, addr) \
    asm volatile("ldmatrix.sync.aligned.m8n8.x4.shared.b16 {%0,%1,%2,%3}, [%4];" \
                 : "=r"(r0), "=r"(r1), "=r"(r2), "=r"(r3) : "r"(addr))

#define LDSM2(r0, r1, addr) \
    asm volatile("ldmatrix.sync.aligned.m8n8.x2.shared.b16 {%0,%1}, [%2];" \
                 : "=r"(r0), "=r"(r1) : "r"(addr))

#define MMA16816(d, a, b0, b1) \
    asm volatile("mma.sync.aligned.m16n8k16.row.col.f32.bf16.bf16.f32 " \
                 "{%0,%1,%2,%3}, {%4,%5,%6,%7}, {%8,%9}, {%0,%1,%2,%3};" \
                 : "+f"(d[0]), "+f"(d[1]), "+f"(d[2]), "+f"(d[3]) \
                 : "r"(a[0]), "r"(a[1]), "r"(a[2]), "r"(a[3]), "r"(b0), "r"(b1))

#define MMAF16(d, a, b0, b1) \
    asm volatile("mma.sync.aligned.m16n8k16.row.col.f32.f16.f16.f32 " \
                 "{%0,%1,%2,%3}, {%4,%5,%6,%7}, {%8,%9}, {%0,%1,%2,%3};" \
                 : "+f"(d[0]), "+f"(d[1]), "+f"(d[2]), "+f"(d[3]) \
                 : "r"(a[0]), "r"(a[1]), "r"(a[2]), "r"(a[3]), "r"(b0), "r"(b1))

// bulk async copy (sm_90 base) + mbarrier
#define BULK_G2S(dst, src, bytes, mbar) \
    asm volatile("cp.async.bulk.shared::cluster.global.mbarrier::complete_tx::bytes " \
                 "[%0], [%1], %2, [%3];" \
                 :: "r"(dst), "l"(src), "r"(bytes), "r"(mbar) : "memory")
#define MBAR_INIT(mbar, cnt) \
    asm volatile("mbarrier.init.shared.b64 [%0], %1;" :: "r"(mbar), "r"(cnt) : "memory")
#define MBAR_INVAL(mbar) \
    asm volatile("mbarrier.inval.shared.b64 [%0];" :: "r"(mbar) : "memory")
#define MBAR_EXPECT(mbar, bytes) \
    asm volatile("mbarrier.arrive.expect_tx.shared.b64 _, [%0], %1;" \
                 :: "r"(mbar), "r"(bytes) : "memory")
#define MBAR_WAIT(mbar, par) do { \
    asm volatile("{\n\t.reg .pred P;\n\tW%=:\n\t" \
        "mbarrier.try_wait.parity.acquire.cta.shared::cta.b64 P, [%0], %1, 0x989680;\n\t" \
        "@!P bra W%=;\n\t}" :: "r"(mbar), "r"(par) : "memory"); \
} while (0)

#define CP_ASYNC16(saddr, gptr) \
    asm volatile("cp.async.cg.shared.global [%0], [%1], 16;" \
                 :: "r"(saddr), "l"(gptr) : "memory")
#define CP_COMMIT() asm volatile("cp.async.commit_group;" ::: "memory")
#define CP_WAIT1()  asm volatile("cp.async.wait_group 1;" ::: "memory")
#define CP_WAIT0()  asm volatile("cp.async.wait_group 0;" ::: "memory")

__device__ __forceinline__ uint32_t smem_u32(const void* p) {
    uint32_t a;
    asm("{ .reg .u64 t; cvta.to.shared.u64 t, %1; cvt.u32.u64 %0, t; }" : "=r"(a) : "l"(p));
    return a;
}

// ---------------- bf16 split prep ----------------
__global__ void split_bf16_kernel(const float* __restrict__ src,
                                  __nv_bfloat16* __restrict__ hi,
                                  __nv_bfloat16* __restrict__ lo, size_t n) {
    size_t i = (size_t)blockIdx.x * blockDim.x + threadIdx.x;
    if (i >= n) return;
    float a = src[i];
    __nv_bfloat16 h = __float2bfloat16(a);
    hi[i] = h;
    lo[i] = __float2bfloat16(a - __bfloat162float(h));
}

// ---------------- zero hidden state (buf 0, both splits) ----------------
__global__ void zero_h_kernel() {
    int i = blockIdx.x * blockDim.x + threadIdx.x;   // 65536
    g_hAhi[0][i] = __float2half(0.0f);
    g_hAlo[0][i] = __float2half(0.0f);
}

// ---------------- tensor-core gx GEMM (R13 cp.async version, passing) ------
#define KC 32
#define PITCH 40
#define TILE_B (128 * PITCH * 2)      // 10240 bytes per tile
#define GEMM_SMEM (2 * 4 * TILE_B)    // 81920 bytes

__global__ void __launch_bounds__(256, 2)
gemm_mma(const __nv_bfloat16* __restrict__ Ahi, const __nv_bfloat16* __restrict__ Alo,
         const __nv_bfloat16* __restrict__ Whi, const __nv_bfloat16* __restrict__ Wlo,
         const float* __restrict__ bias, int K)
{
    extern __shared__ char gsm[];
    uint32_t base = smem_u32(gsm);

    int tid  = threadIdx.x;
    int wid  = tid >> 5, lane = tid & 31;
    int dir  = blockIdx.z;
    int n0   = blockIdx.x * 128;
    int m0   = blockIdx.y * 128;
    int wm   = wid >> 1;
    int wn   = wid & 1;

    const __nv_bfloat16* bhi = Whi + (size_t)dir * Gc * K;
    const __nv_bfloat16* blo = Wlo + (size_t)dir * Gc * K;
    float* C = g_gx + (size_t)dir * M_TOK * Gc;
    const float* bp = bias + dir * Gc;

    float acc[2][8][4];
#pragma unroll
    for (int i = 0; i < 2; i++)
#pragma unroll
        for (int j = 0; j < 8; j++)
#pragma unroll
            for (int q = 0; q < 4; q++) acc[i][j][q] = 0.0f;

    int a_row = (lane & 15);
    int a_col = (lane >> 4) * 8;
    int b_row = (lane & 7) + ((lane >> 4) & 1) * 8;
    int b_col = ((lane >> 3) & 1) * 8;

    const int nchunks = K / KC;

    auto stage = [&](int c, int buf) {
        int k0 = c * KC;
#pragma unroll
        for (int p = 0; p < 8; p++) {
            int idx = p * 256 + tid;          // 0..2047
            int tile = idx >> 9;              // 0..3
            int g2   = idx & 511;
            int r    = g2 >> 2;
            int c4   = g2 & 3;
            const __nv_bfloat16* src;
            if (tile == 0)      src = Ahi + (size_t)(m0 + r) * K + k0 + c4 * 8;
            else if (tile == 1) src = Alo + (size_t)(m0 + r) * K + k0 + c4 * 8;
            else if (tile == 2) src = bhi + (size_t)(n0 + r) * K + k0 + c4 * 8;
            else                src = blo + (size_t)(n0 + r) * K + k0 + c4 * 8;
            uint32_t dst = base + (uint32_t)((buf * 4 + tile) * TILE_B)
                         + (uint32_t)((r * PITCH + c4 * 8) * 2);
            CP_ASYNC16(dst, (const void*)src);
        }
        CP_COMMIT();
    };

    stage(0, 0);
    for (int c = 0; c < nchunks; c++) {
        if (c + 1 < nchunks) { stage(c + 1, (c + 1) & 1); CP_WAIT1(); }
        else                 { CP_WAIT0(); }
        __syncthreads();

        uint32_t bb = base + (uint32_t)((c & 1) * 4 * TILE_B);
        uint32_t uAhi = bb, uAlo = bb + TILE_B, uBhi = bb + 2 * TILE_B, uBlo = bb + 3 * TILE_B;

#pragma unroll
        for (int kk = 0; kk < 2; kk++) {
            int k16 = kk * 16;
            uint32_t ahi[2][4], alo[2][4];
#pragma unroll
            for (int mt = 0; mt < 2; mt++) {
                uint32_t off = 2u * ((wm * 32 + mt * 16 + a_row) * PITCH + k16 + a_col);
                LDSM4(ahi[mt][0], ahi[mt][1], ahi[mt][2], ahi[mt][3], uAhi + off);
                LDSM4(alo[mt][0], alo[mt][1], alo[mt][2], alo[mt][3], uAlo + off);
            }
#pragma unroll
            for (int np = 0; np < 4; np++) {
                uint32_t off = 2u * ((wn * 64 + np * 16 + b_row) * PITCH + k16 + b_col);
                uint32_t bh0, bh1, bh2, bh3, bl0, bl1, bl2, bl3;
                LDSM4(bh0, bh1, bh2, bh3, uBhi + off);
                LDSM4(bl0, bl1, bl2, bl3, uBlo + off);
#pragma unroll
                for (int mt = 0; mt < 2; mt++) {
                    MMA16816(acc[mt][np * 2 + 0], ahi[mt], bh0, bh1);
                    MMA16816(acc[mt][np * 2 + 0], ahi[mt], bl0, bl1);
                    MMA16816(acc[mt][np * 2 + 0], alo[mt], bh0, bh1);
                    MMA16816(acc[mt][np * 2 + 1], ahi[mt], bh2, bh3);
                    MMA16816(acc[mt][np * 2 + 1], ahi[mt], bl2, bl3);
                    MMA16816(acc[mt][np * 2 + 1], alo[mt], bh2, bh3);
                }
            }
        }
        __syncthreads();
    }

    // epilogue: write recurrence-friendly gx layout
#pragma unroll
    for (int mt = 0; mt < 2; mt++) {
#pragma unroll
        for (int nt = 0; nt < 8; nt++) {
            int row = m0 + wm * 32 + mt * 16 + (lane >> 2);
            int col = n0 + wn * 64 + nt * 8 + (lane & 3) * 2;
            float b0 = bp[col], b1 = bp[col + 1];
            int g = col >> 9, j = col & 511;
            int jc = j >> 4, jl = j & 15;
#pragma unroll
            for (int half = 0; half < 2; half++) {
                int r = row + half * 8;
                int bb2 = r >> 9, tt = r & 511;
                size_t addr = (size_t)tt * 98304 + (size_t)(bb2 >> 5) * 49152
                            + jc * 1536 + g * 512 + (bb2 & 31) * 16 + jl;
                float2 v = half ? make_float2(acc[mt][nt][2] + b0, acc[mt][nt][3] + b1)
                                : make_float2(acc[mt][nt][0] + b0, acc[mt][nt][1] + b1);
                *(float2*)&C[addr] = v;
            }
        }
    }
}

// ---------------- persistent MMA recurrence (R12 structure, fp16 2-product) -
#define RPITCH 520
#define PG 41
#define OFF_W   0
#define SZ_W    (48 * RPITCH * 2)               // 49920 (single fp16 W)
#define OFF_HHI (OFF_W + SZ_W)                  // [kh][32][256] swizzled
#define SZ_H    (2 * 32 * 256 * 2)              // 32768
#define OFF_HLO (OFF_HHI + SZ_H)
#define OFF_G   (OFF_HLO + SZ_H)                // [48][41] floats (K-half 0)
#define OFF_G2  (OFF_G + 48 * PG * 4)           // [48][41] floats (K-half 1)
#define OFF_GX  (OFF_G2 + 48 * PG * 4)          // [2][1536] floats
#define OFF_X   (OFF_GX + 12288)                // [32][16] floats
#define OFF_MB  (OFF_X + 2048)                  // 4 mbarriers
#define PERSIST_SMEM (OFF_MB + 64)              // 145664 bytes

__global__ void __launch_bounds__(256, 1)
gru_persist_mma(const float* __restrict__ w_hh,
                const float* __restrict__ b_hh,
                float* __restrict__ out_l1,
                int layer)
{
    extern __shared__ char sm[];
    __half* sW   = (__half*)(sm + OFF_W);
    __half* sHhi = (__half*)(sm + OFF_HHI);
    __half* sHlo = (__half*)(sm + OFF_HLO);
    float* sG  = (float*)(sm + OFF_G);
    float* sG2 = (float*)(sm + OFF_G2);
    float* sGX = (float*)(sm + OFF_GX);
    float* sX  = (float*)(sm + OFF_X);

    int tid = threadIdx.x, lane = tid & 31, wid = tid >> 5;
    int dir   = blockIdx.z;
    int bhalf = blockIdx.y;
    int j0    = blockIdx.x * 16;
    int b0    = bhalf * 32;
    int grp   = dir * 2 + bhalf;
    int myhalf = blockIdx.x >> 4;          // j0 < 256 -> half 0
    int ilo = (grp * 2 + 0) * 32;
    int ihi = (grp * 2 + 1) * 32;
    int imine = (grp * 2 + myhalf) * 32;

    int gbase_lo = g_bar_gen2[ilo];
    int gbase_hi = g_bar_gen2[ihi];
    int gbase_mine = myhalf ? gbase_hi : gbase_lo;

    uint32_t sbase = smem_u32(sm);
    uint32_t mb_h0 = sbase + OFF_MB;
    uint32_t mb_h1 = sbase + OFF_MB + 8;
    uint32_t mb_g0 = sbase + OFF_MB + 16;
    uint32_t mb_g1 = sbase + OFF_MB + 24;

    // split-K warp mapping: warps 0-3 -> K[0,256); warps 4-7 -> K[256,512)
    int wlocal  = wid & 3;
    int khalf_w = wid >> 2;
    int wm  = wlocal & 1;
    int wn2 = wlocal >> 1;
    int nbase = wn2 * 24;
    int m_base = wm * 16;
    float* sGmine = khalf_w ? sG2 : sG;

    int jl = tid & 15;
    int lbase = tid >> 4;
    int jglob = j0 + jl;

    int lb2 = tid >> 3;          // writer batch 0..31
    int jp  = (tid & 7) * 2;     // writer j-pair

    // one-time: load W slice as single fp16 (48 rows, gate-major r = g*16 + jj)
    const float* W = w_hh + (size_t)dir * Gc * Hc;
    for (int idx = tid; idx < 48 * 512; idx += 256) {
        int r = idx >> 9, k = idx & 511;
        int gg = r >> 4, jj = r & 15;
        float w = W[(size_t)(gg * Hc + j0 + jj) * Hc + k];
        sW[r * RPITCH + k] = __float2half(w);
    }
    float br = __ldg(&b_hh[dir * Gc + jglob]);
    float bz = __ldg(&b_hh[dir * Gc + Hc + jglob]);
    float bn = __ldg(&b_hh[dir * Gc + 2 * Hc + jglob]);

    const float* gxblk = g_gx + (size_t)dir * M_TOK * Gc
                       + (size_t)bhalf * 49152 + (size_t)blockIdx.x * 1536;
    float* hs = (layer == 0) ? g_h0out : out_l1;

    uint32_t uW   = smem_u32(sW);
    uint32_t uHhi = smem_u32(sHhi), uHlo = smem_u32(sHlo);
    uint32_t uGX  = smem_u32(sGX);

    int a_row = lane & 15, a_col = (lane >> 4) * 8;
    int b_row = (lane & 7) + ((lane >> 4) & 1) * 8, b_col = ((lane >> 3) & 1) * 8;
    int b_row2 = 16 + (lane & 7);

    // writer constants (swizzled global h layout)
    int wkh   = j0 >> 8;
    int wjloc = (j0 & 255) + jp;
    int wunit = (wjloc >> 3) ^ (lb2 & 7);
    int woff  = ((dir * 2 + wkh) * 64 + (b0 + lb2)) * 256 + (wunit << 3) + (wjloc & 7);
    // hp reader constants
    int hkh   = jglob >> 8;
    int hjloc = jglob & 255;

    if (tid == 0) {
        MBAR_INIT(mb_h0, 1); MBAR_INIT(mb_h1, 1);
        MBAR_INIT(mb_g0, 1); MBAR_INIT(mb_g1, 1);
    }
    __syncthreads();

    // prologue: gx(0) bulk into buf 0
    if (tid == 0) {
        int t0 = dir ? (Tc - 1) : 0;
        MBAR_EXPECT(mb_g0, 6144u);
        BULK_G2S(uGX, (const void*)(gxblk + (size_t)t0 * 98304), 6144u, mb_g0);
    }
    int gxph0 = 0, gxph1 = 0;

    for (int s = 0; s < Tc; s++) {
        int rbuf = s & 1;
        int par = s & 1;
        int t = dir ? (Tc - 1 - s) : s;
        const __half* hAhi = g_hAhi[rbuf];
        const __half* hAlo = g_hAlo[rbuf];
        __half* wAhi = g_hAhi[rbuf ^ 1];
        __half* wAlo = g_hAlo[rbuf ^ 1];

        // tid0: poll lo half ready -> issue k-half-0 bulks; then hi half
        if (tid == 0) {
            if (s > 0) while (g_bar_gen2[ilo] - gbase_lo < s) { }
            size_t src0 = (size_t)((dir * 2 + 0) * 64 + b0) * 256;
            MBAR_EXPECT(mb_h0, 32768u);
            BULK_G2S(uHhi, (const void*)(hAhi + src0), 16384u, mb_h0);
            BULK_G2S(uHlo, (const void*)(hAlo + src0), 16384u, mb_h0);
            if (s > 0) while (g_bar_gen2[ihi] - gbase_hi < s) { }
            size_t src1 = (size_t)((dir * 2 + 1) * 64 + b0) * 256;
            MBAR_EXPECT(mb_h1, 32768u);
            BULK_G2S(uHhi + 16384, (const void*)(hAhi + src1), 16384u, mb_h1);
            BULK_G2S(uHlo + 16384, (const void*)(hAlo + src1), 16384u, mb_h1);
        }

        float acc[3][4];
#pragma unroll
        for (int i = 0; i < 3; i++)
#pragma unroll
            for (int q = 0; q < 4; q++) acc[i][q] = 0.0f;

        // ---- split-K MMA: warp group khalf_w handles its K half ----
        MBAR_WAIT(khalf_w ? mb_h1 : mb_h0, par);
        {
            uint32_t hbase = khalf_w ? 16384u : 0u;
            int kwb = khalf_w * 16;
#pragma unroll
            for (int kk = 0; kk < 16; kk++) {
                int k16 = kwb + kk;
                int unitA = kk * 2 + (a_col >> 3);
                int rowA = m_base + a_row;
                uint32_t offA = hbase + (uint32_t)(rowA * 512 + ((unitA ^ (rowA & 7)) << 4));
                uint32_t ahi[4], alo[4];
                LDSM4(ahi[0], ahi[1], ahi[2], ahi[3], uHhi + offA);
                LDSM4(alo[0], alo[1], alo[2], alo[3], uHlo + offA);

                uint32_t offB = (uint32_t)(((nbase + b_row) * RPITCH + k16 * 16 + b_col) * 2);
                uint32_t bh0, bh1, bh2, bh3;
                LDSM4(bh0, bh1, bh2, bh3, uW + offB);
                MMAF16(acc[0], ahi, bh0, bh1);
                MMAF16(acc[0], alo, bh0, bh1);
                MMAF16(acc[1], ahi, bh2, bh3);
                MMAF16(acc[1], alo, bh2, bh3);

                uint32_t offB2 = (uint32_t)(((nbase + b_row2) * RPITCH + k16 * 16 + b_col) * 2);
                uint32_t ch0, ch1;
                LDSM2(ch0, ch1, uW + offB2);
                MMAF16(acc[2], ahi, ch0, ch1);
                MMAF16(acc[2], alo, ch0, ch1);
            }
            // dump partial gh to own buffer [gate row][batch row]
#pragma unroll
            for (int nt = 0; nt < 3; nt++) {
                int c0 = nbase + nt * 8 + (lane & 3) * 2;
                int r0 = m_base + (lane >> 2);
                sGmine[c0 * PG + r0]           = acc[nt][0];
                sGmine[(c0 + 1) * PG + r0]     = acc[nt][1];
                sGmine[c0 * PG + r0 + 8]       = acc[nt][2];
                sGmine[(c0 + 1) * PG + r0 + 8] = acc[nt][3];
            }
        }
        __syncthreads();

        // gx ready for this step?
        if (rbuf == 0) { MBAR_WAIT(mb_g0, gxph0); gxph0 ^= 1; }
        else           { MBAR_WAIT(mb_g1, gxph1); gxph1 ^= 1; }

        // gate math (partials from both K halves)
        const float* gxs = sGX + rbuf * 1536;
#pragma unroll
        for (int rep = 0; rep < 2; rep++) {
            int lb = lbase + rep * 16;
            float ghr = sG[jl * PG + lb]        + sG2[jl * PG + lb];
            float ghz = sG[(16 + jl) * PG + lb] + sG2[(16 + jl) * PG + lb];
            float ghn = sG[(32 + jl) * PG + lb] + sG2[(32 + jl) * PG + lb];
            float gr = gxs[lb * 16 + jl];
            float gz = gxs[512 + lb * 16 + jl];
            float gn = gxs[1024 + lb * 16 + jl];
            int hidx = hkh * 8192 + lb * 256 + (((hjloc >> 3) ^ (lb & 7)) << 3) + (hjloc & 7);
            float hp = __half2float(sHhi[hidx]) + __half2float(sHlo[hidx]);
            float rr = 1.0f / (1.0f + __expf(-(gr + ghr + br)));
            float zz = 1.0f / (1.0f + __expf(-(gz + ghz + bz)));
            float xa = gn + rr * (ghn + bn);
            float e2 = __expf(2.0f * xa);
            float nn = 1.0f - __fdividef(2.0f, e2 + 1.0f);
            sX[lb * 16 + jl] = (1.0f - zz) * nn + zz * hp;
        }
        __syncthreads();

        // h_new global write (swizzled layout): one half2 per array per thread
        {
            float v0 = sX[lb2 * 16 + jp];
            float v1 = sX[lb2 * 16 + jp + 1];
            __half h0 = __float2half(v0), h1 = __float2half(v1);
            __half2 hi01 = {h0, h1};
            __half2 lo01 = {__float2half(v0 - __half2float(h0)),
                            __float2half(v1 - __half2float(h1))};
            *(__half2*)(wAhi + woff) = hi01;
            *(__half2*)(wAlo + woff) = lo01;
        }
        __syncthreads();

        // arrive at own sub-barrier (skip on last step)
        if (s != Tc - 1 && tid == 0) {
            __threadfence();
            asm volatile("fence.proxy.async;" ::: "memory");
            int old = atomicAdd(&g_bar_cnt[imine], 1);
            if (old == NHALF - 1) {
                g_bar_cnt[imine] = 0;
                __threadfence();
                g_bar_gen2[imine] = gbase_mine + s + 1;
            }
        }

        // off-critical-path: hs output (coalesced)
        {
            float2 xv = make_float2(sX[lb2 * 16 + jp], sX[lb2 * 16 + jp + 1]);
            *(float2*)&hs[((size_t)(b0 + lb2) * Tc + t) * (2 * Hc) + dir * Hc + j0 + jp] = xv;
        }
        // gx bulk prefetch for s+1
        if (s != Tc - 1 && tid == 0) {
            int tn = dir ? (Tc - 2 - s) : (s + 1);
            uint32_t mb = ((s + 1) & 1) ? mb_g1 : mb_g0;
            MBAR_EXPECT(mb, 6144u);
            BULK_G2S(uGX + ((s + 1) & 1) * 6144,
                     (const void*)(gxblk + (size_t)tn * 98304), 6144u, mb);
        }
    }

    __syncthreads();
    if (tid == 0) {
        MBAR_INVAL(mb_h0); MBAR_INVAL(mb_h1);
        MBAR_INVAL(mb_g0); MBAR_INVAL(mb_g1);
    }
}

// ---------------- copy final hidden states (de-swizzle) ----------------
__global__ void hy_copy_kernel(float* __restrict__ d_out, int layer) {
    int i = blockIdx.x * blockDim.x + threadIdx.x;   // 0..65535
    int dir = i >> 15;
    int rem = i & 32767;                              // = b*512 + j
    int b = rem >> 9;
    int j = rem & 511;
    int kh = j >> 8, jloc = j & 255;
    int off = ((dir * 2 + kh) * 64 + b) * 256 + ((((jloc >> 3) ^ (b & 7))) << 3) + (jloc & 7);
    d_out[HY_OFF + (size_t)(2 * layer + dir) * Bc * Hc + rem] =
        __half2float(g_hAhi[0][off]) + __half2float(g_hAlo[0][off]);
}

// ---------------- launch ----------------
extern "C" void kernel_launch(void* const* d_in, const int* in_sizes, int n_in,
                              void* d_out, int out_size)
{
    const float* xs    = (const float*)d_in[0];
    const float* w_ih0 = (const float*)d_in[1];
    const float* w_hh0 = (const float*)d_in[2];
    const float* b_ih0 = (const float*)d_in[3];
    const float* b_hh0 = (const float*)d_in[4];
    const float* w_ih1 = (const float*)d_in[5];
    const float* w_hh1 = (const float*)d_in[6];
    const float* b_ih1 = (const float*)d_in[7];
    const float* b_hh1 = (const float*)d_in[8];
    float* out = (float*)d_out;

    cudaFuncSetAttribute(gru_persist_mma,
                         cudaFuncAttributeMaxDynamicSharedMemorySize, PERSIST_SMEM);
    cudaFuncSetAttribute(gemm_mma,
                         cudaFuncAttributeMaxDynamicSharedMemorySize, GEMM_SMEM);

    __nv_bfloat16 *xs_hi, *xs_lo, *h0_hi, *h0_lo, *w0_hi, *w0_lo, *w1_hi, *w1_lo;
    cudaGetSymbolAddress((void**)&xs_hi, g_xs_hi);
    cudaGetSymbolAddress((void**)&xs_lo, g_xs_lo);
    cudaGetSymbolAddress((void**)&h0_hi, g_h0_hi);
    cudaGetSymbolAddress((void**)&h0_lo, g_h0_lo);
    cudaGetSymbolAddress((void**)&w0_hi, g_w0_hi);
    cudaGetSymbolAddress((void**)&w0_lo, g_w0_lo);
    cudaGetSymbolAddress((void**)&w1_hi, g_w1_hi);
    cudaGetSymbolAddress((void**)&w1_lo, g_w1_lo);
    float* h0out;
    cudaGetSymbolAddress((void**)&h0out, g_h0out);

    dim3 gemm_grid(Gc / 128, M_TOK / 128, 2);   // (12, 256, 2)
    dim3 persist_grid(32, 2, 2);                // 128 blocks

    size_t n_w0 = (size_t)2 * Gc * Ec;
    size_t n_w1 = (size_t)2 * Gc * 2 * Hc;
    size_t n_xs = (size_t)M_TOK * Ec;
    size_t n_h0 = (size_t)M_TOK * 2 * Hc;

    split_bf16_kernel<<<(unsigned)((n_w0 + 255) / 256), 256>>>(w_ih0, w0_hi, w0_lo, n_w0);
    split_bf16_kernel<<<(unsigned)((n_w1 + 255) / 256), 256>>>(w_ih1, w1_hi, w1_lo, n_w1);
    split_bf16_kernel<<<(unsigned)((n_xs + 255) / 256), 256>>>(xs, xs_hi, xs_lo, n_xs);

    // ---- layer 0 ----
    gemm_mma<<<gemm_grid, 256, GEMM_SMEM>>>(xs_hi, xs_lo, w0_hi, w0_lo, b_ih0, Ec);
    zero_h_kernel<<<(2 * 2 * Bc * 256) / 256, 256>>>();
    gru_persist_mma<<<persist_grid, 256, PERSIST_SMEM>>>(w_hh0, b_hh0, out, 0);
    hy_copy_kernel<<<(2 * Bc * Hc) / 256, 256>>>(out, 0);

    // ---- layer 1 ----
    split_bf16_kernel<<<(unsigned)((n_h0 + 255) / 256), 256>>>(h0out, h0_hi, h0_lo, n_h0);
    gemm_mma<<<gemm_grid, 256, GEMM_SMEM>>>(h0_hi, h0_lo, w1_hi, w1_lo, b_ih1, 2 * Hc);
    zero_h_kernel<<<(2 * 2 * Bc * 256) / 256, 256>>>();
    gru_persist_mma<<<persist_grid, 256, PERSIST_SMEM>>>(w_hh1, b_hh1, out, 1);
    hy_copy_kernel<<<(2 * Bc * Hc) / 256, 256>>>(out, 1);
}

// round 15
// speedup vs baseline: 1.3954x; 1.2064x over previous
#include <cuda_runtime.h>
#include <cuda_bf16.h>
#include <cuda_fp16.h>
#include <cstdint>
#include <math.h>

#define Bc 64
#define Tc 512
#define Ec 512
#define Hc 512
#define Gc 1536            // 3*H
#define M_TOK (Bc*Tc)      // 32768 tokens
#define HY_OFF ((size_t)Bc*Tc*2*Hc)
#define NHALF 16           // blocks per sub-barrier half

// ---------------- device scratch ----------------
// gx layout: [dir][t][bhalf][jc(32)][g(3)][b_local(32)][jl(16)]
__device__ float g_gx[(size_t)2*M_TOK*Gc];
__device__ float g_h0out[(size_t)M_TOK*2*Hc];    // layer0 output [b][t][2H]

// h state single fp16, layout [buf][(dir*2+jhalf)*64 + b][256] with XOR swizzle
__device__ __half g_hA[2][2*2*64*256];

// fp16 operands for gx GEMMs
__device__ __half g_xs_hi[(size_t)M_TOK*Ec],  g_xs_lo[(size_t)M_TOK*Ec];
__device__ __half g_h0_hi[(size_t)M_TOK*2*Hc], g_h0_lo[(size_t)M_TOK*2*Hc];
__device__ __half g_w0[(size_t)2*Gc*Ec];
__device__ __half g_w1[(size_t)2*Gc*2*Hc];

// sub-barrier state: [group(4)][half(2)], padded lines
__device__ int g_bar_cnt[4 * 2 * 32];
__device__ volatile int g_bar_gen2[4 * 2 * 32];

// warp-mma helpers (base PTX)
#define LDSM4(r0, r1, r2, r3, addr) \
    asm volatile("ldmatrix.sync.aligned.m8n8.x4.shared.b16 {%0,%1,%2,%3}, [%4];" \
                 : "=r"(r0), "=r"(r1), "=r"(r2), "=r"(r3) : "r"(addr))

#define LDSM2(r0, r1, addr) \
    asm volatile("ldmatrix.sync.aligned.m8n8.x2.shared.b16 {%0,%1}, [%2];" \
                 : "=r"(r0), "=r"(r1) : "r"(addr))

#define MMAF16(d, a, b0, b1) \
    asm volatile("mma.sync.aligned.m16n8k16.row.col.f32.f16.f16.f32 " \
                 "{%0,%1,%2,%3}, {%4,%5,%6,%7}, {%8,%9}, {%0,%1,%2,%3};" \
                 : "+f"(d[0]), "+f"(d[1]), "+f"(d[2]), "+f"(d[3]) \
                 : "r"(a[0]), "r"(a[1]), "r"(a[2]), "r"(a[3]), "r"(b0), "r"(b1))

// bulk async copy (sm_90 base) + mbarrier
#define BULK_G2S(dst, src, bytes, mbar) \
    asm volatile("cp.async.bulk.shared::cluster.global.mbarrier::complete_tx::bytes " \
                 "[%0], [%1], %2, [%3];" \
                 :: "r"(dst), "l"(src), "r"(bytes), "r"(mbar) : "memory")
#define MBAR_INIT(mbar, cnt) \
    asm volatile("mbarrier.init.shared.b64 [%0], %1;" :: "r"(mbar), "r"(cnt) : "memory")
#define MBAR_INVAL(mbar) \
    asm volatile("mbarrier.inval.shared.b64 [%0];" :: "r"(mbar) : "memory")
#define MBAR_EXPECT(mbar, bytes) \
    asm volatile("mbarrier.arrive.expect_tx.shared.b64 _, [%0], %1;" \
                 :: "r"(mbar), "r"(bytes) : "memory")
#define MBAR_WAIT(mbar, par) do { \
    asm volatile("{\n\t.reg .pred P;\n\tW%=:\n\t" \
        "mbarrier.try_wait.parity.acquire.cta.shared::cta.b64 P, [%0], %1, 0x989680;\n\t" \
        "@!P bra W%=;\n\t}" :: "r"(mbar), "r"(par) : "memory"); \
} while (0)

#define CP_ASYNC16(saddr, gptr) \
    asm volatile("cp.async.cg.shared.global [%0], [%1], 16;" \
                 :: "r"(saddr), "l"(gptr) : "memory")
#define CP_COMMIT() asm volatile("cp.async.commit_group;" ::: "memory")
#define CP_WAIT1()  asm volatile("cp.async.wait_group 1;" ::: "memory")
#define CP_WAIT0()  asm volatile("cp.async.wait_group 0;" ::: "memory")

__device__ __forceinline__ uint32_t smem_u32(const void* p) {
    uint32_t a;
    asm("{ .reg .u64 t; cvta.to.shared.u64 t, %1; cvt.u32.u64 %0, t; }" : "=r"(a) : "l"(p));
    return a;
}

// ---------------- fp16 prep ----------------
__global__ void split_fp16_kernel(const float* __restrict__ src,
                                  __half* __restrict__ hi,
                                  __half* __restrict__ lo, size_t n) {
    size_t i = (size_t)blockIdx.x * blockDim.x + threadIdx.x;
    if (i >= n) return;
    float a = src[i];
    __half h = __float2half(a);
    hi[i] = h;
    lo[i] = __float2half(a - __half2float(h));
}

__global__ void conv_fp16_kernel(const float* __restrict__ src,
                                 __half* __restrict__ dst, size_t n) {
    size_t i = (size_t)blockIdx.x * blockDim.x + threadIdx.x;
    if (i >= n) return;
    dst[i] = __float2half(src[i]);
}

// ---------------- zero hidden state (buf 0) ----------------
__global__ void zero_h_kernel() {
    int i = blockIdx.x * blockDim.x + threadIdx.x;   // 65536
    g_hA[0][i] = __float2half(0.0f);
}

// ---------------- tensor-core gx GEMM (fp16 2-product, cp.async 2-stage) ---
#define KC 32
#define PITCH 40
#define TILE_B (128 * PITCH * 2)      // 10240 bytes per tile
#define GEMM_SMEM (2 * 3 * TILE_B)    // 61440 bytes

__global__ void __launch_bounds__(256, 2)
gemm_mma(const __half* __restrict__ Ahi, const __half* __restrict__ Alo,
         const __half* __restrict__ Wp,
         const float* __restrict__ bias, int K)
{
    extern __shared__ char gsm[];
    uint32_t base = smem_u32(gsm);

    int tid  = threadIdx.x;
    int wid  = tid >> 5, lane = tid & 31;
    int dir  = blockIdx.z;
    int n0   = blockIdx.x * 128;
    int m0   = blockIdx.y * 128;
    int wm   = wid >> 1;
    int wn   = wid & 1;

    const __half* Wd = Wp + (size_t)dir * Gc * K;
    float* C = g_gx + (size_t)dir * M_TOK * Gc;
    const float* bp = bias + dir * Gc;

    float acc[2][8][4];
#pragma unroll
    for (int i = 0; i < 2; i++)
#pragma unroll
        for (int j = 0; j < 8; j++)
#pragma unroll
            for (int q = 0; q < 4; q++) acc[i][j][q] = 0.0f;

    int a_row = (lane & 15);
    int a_col = (lane >> 4) * 8;
    int b_row = (lane & 7) + ((lane >> 4) & 1) * 8;
    int b_col = ((lane >> 3) & 1) * 8;

    const int nchunks = K / KC;

    auto stage = [&](int c, int buf) {
        int k0 = c * KC;
#pragma unroll
        for (int p = 0; p < 6; p++) {
            int idx = p * 256 + tid;          // 0..1535
            int tile = idx >> 9;              // 0..2
            int g2   = idx & 511;
            int r    = g2 >> 2;
            int c4   = g2 & 3;
            const __half* src;
            if (tile == 0)      src = Ahi + (size_t)(m0 + r) * K + k0 + c4 * 8;
            else if (tile == 1) src = Alo + (size_t)(m0 + r) * K + k0 + c4 * 8;
            else                src = Wd  + (size_t)(n0 + r) * K + k0 + c4 * 8;
            uint32_t dst = base + (uint32_t)((buf * 3 + tile) * TILE_B)
                         + (uint32_t)((r * PITCH + c4 * 8) * 2);
            CP_ASYNC16(dst, (const void*)src);
        }
        CP_COMMIT();
    };

    stage(0, 0);
    for (int c = 0; c < nchunks; c++) {
        if (c + 1 < nchunks) { stage(c + 1, (c + 1) & 1); CP_WAIT1(); }
        else                 { CP_WAIT0(); }
        __syncthreads();

        uint32_t bb = base + (uint32_t)((c & 1) * 3 * TILE_B);
        uint32_t uAhi = bb, uAlo = bb + TILE_B, uB = bb + 2 * TILE_B;

#pragma unroll
        for (int kk = 0; kk < 2; kk++) {
            int k16 = kk * 16;
            uint32_t ahi[2][4], alo[2][4];
#pragma unroll
            for (int mt = 0; mt < 2; mt++) {
                uint32_t off = 2u * ((wm * 32 + mt * 16 + a_row) * PITCH + k16 + a_col);
                LDSM4(ahi[mt][0], ahi[mt][1], ahi[mt][2], ahi[mt][3], uAhi + off);
                LDSM4(alo[mt][0], alo[mt][1], alo[mt][2], alo[mt][3], uAlo + off);
            }
#pragma unroll
            for (int np = 0; np < 4; np++) {
                uint32_t off = 2u * ((wn * 64 + np * 16 + b_row) * PITCH + k16 + b_col);
                uint32_t bh0, bh1, bh2, bh3;
                LDSM4(bh0, bh1, bh2, bh3, uB + off);
#pragma unroll
                for (int mt = 0; mt < 2; mt++) {
                    MMAF16(acc[mt][np * 2 + 0], ahi[mt], bh0, bh1);
                    MMAF16(acc[mt][np * 2 + 0], alo[mt], bh0, bh1);
                    MMAF16(acc[mt][np * 2 + 1], ahi[mt], bh2, bh3);
                    MMAF16(acc[mt][np * 2 + 1], alo[mt], bh2, bh3);
                }
            }
        }
        __syncthreads();
    }

    // epilogue: write recurrence-friendly gx layout
#pragma unroll
    for (int mt = 0; mt < 2; mt++) {
#pragma unroll
        for (int nt = 0; nt < 8; nt++) {
            int row = m0 + wm * 32 + mt * 16 + (lane >> 2);
            int col = n0 + wn * 64 + nt * 8 + (lane & 3) * 2;
            float b0 = bp[col], b1 = bp[col + 1];
            int g = col >> 9, j = col & 511;
            int jc = j >> 4, jl = j & 15;
#pragma unroll
            for (int half = 0; half < 2; half++) {
                int r = row + half * 8;
                int bb2 = r >> 9, tt = r & 511;
                size_t addr = (size_t)tt * 98304 + (size_t)(bb2 >> 5) * 49152
                            + jc * 1536 + g * 512 + (bb2 & 31) * 16 + jl;
                float2 v = half ? make_float2(acc[mt][nt][2] + b0, acc[mt][nt][3] + b1)
                                : make_float2(acc[mt][nt][0] + b0, acc[mt][nt][1] + b1);
                *(float2*)&C[addr] = v;
            }
        }
    }
}

// ---------------- persistent MMA recurrence (fp16 single h + W) ------------
#define RPITCH 520
#define PG 41
#define OFF_W   0
#define SZ_W    (48 * RPITCH * 2)               // 49920
#define OFF_H   (OFF_W + SZ_W)                  // [kh(2)][32][256] swizzled
#define SZ_H    (2 * 32 * 256 * 2)              // 32768
#define OFF_G   (OFF_H + SZ_H)                  // [48][41] floats (K-half 0)
#define OFF_G2  (OFF_G + 48 * PG * 4)           // [48][41] floats (K-half 1)
#define OFF_GX  (OFF_G2 + 48 * PG * 4)          // [2][1536] floats
#define OFF_X   (OFF_GX + 12288)                // [32][16] floats
#define OFF_MB  (OFF_X + 2048)                  // 4 mbarriers
#define PERSIST_SMEM (OFF_MB + 64)              // 112832 bytes

__global__ void __launch_bounds__(256, 1)
gru_persist_mma(const float* __restrict__ w_hh,
                const float* __restrict__ b_hh,
                float* __restrict__ out_l1,
                int layer)
{
    extern __shared__ char sm[];
    __half* sW = (__half*)(sm + OFF_W);
    __half* sH = (__half*)(sm + OFF_H);
    float* sG  = (float*)(sm + OFF_G);
    float* sG2 = (float*)(sm + OFF_G2);
    float* sGX = (float*)(sm + OFF_GX);
    float* sX  = (float*)(sm + OFF_X);

    int tid = threadIdx.x, lane = tid & 31, wid = tid >> 5;
    int dir   = blockIdx.z;
    int bhalf = blockIdx.y;
    int j0    = blockIdx.x * 16;
    int b0    = bhalf * 32;
    int grp   = dir * 2 + bhalf;
    int myhalf = blockIdx.x >> 4;          // j0 < 256 -> half 0
    int ilo = (grp * 2 + 0) * 32;
    int ihi = (grp * 2 + 1) * 32;
    int imine = (grp * 2 + myhalf) * 32;

    int gbase_lo = g_bar_gen2[ilo];
    int gbase_hi = g_bar_gen2[ihi];
    int gbase_mine = myhalf ? gbase_hi : gbase_lo;

    uint32_t sbase = smem_u32(sm);
    uint32_t mb_h0 = sbase + OFF_MB;
    uint32_t mb_h1 = sbase + OFF_MB + 8;
    uint32_t mb_g0 = sbase + OFF_MB + 16;
    uint32_t mb_g1 = sbase + OFF_MB + 24;

    // split-K warp mapping: warps 0-3 -> K[0,256); warps 4-7 -> K[256,512)
    int wlocal  = wid & 3;
    int khalf_w = wid >> 2;
    int wm  = wlocal & 1;
    int wn2 = wlocal >> 1;
    int nbase = wn2 * 24;
    int m_base = wm * 16;
    float* sGmine = khalf_w ? sG2 : sG;

    int jl = tid & 15;
    int lbase = tid >> 4;
    int jglob = j0 + jl;

    int lb2 = tid >> 3;          // writer batch 0..31
    int jp  = (tid & 7) * 2;     // writer j-pair

    // one-time: load W slice as fp16 (48 rows, gate-major r = g*16 + jj)
    const float* W = w_hh + (size_t)dir * Gc * Hc;
    for (int idx = tid; idx < 48 * 512; idx += 256) {
        int r = idx >> 9, k = idx & 511;
        int gg = r >> 4, jj = r & 15;
        sW[r * RPITCH + k] = __float2half(W[(size_t)(gg * Hc + j0 + jj) * Hc + k]);
    }
    float br = __ldg(&b_hh[dir * Gc + jglob]);
    float bz = __ldg(&b_hh[dir * Gc + Hc + jglob]);
    float bn = __ldg(&b_hh[dir * Gc + 2 * Hc + jglob]);

    const float* gxblk = g_gx + (size_t)dir * M_TOK * Gc
                       + (size_t)bhalf * 49152 + (size_t)blockIdx.x * 1536;
    float* hs = (layer == 0) ? g_h0out : out_l1;

    uint32_t uW  = smem_u32(sW);
    uint32_t uH  = smem_u32(sH);
    uint32_t uGX = smem_u32(sGX);

    int a_row = lane & 15, a_col = (lane >> 4) * 8;
    int b_row = (lane & 7) + ((lane >> 4) & 1) * 8, b_col = ((lane >> 3) & 1) * 8;
    int b_row2 = 16 + (lane & 7);

    // writer constants (swizzled global h layout)
    int wkh   = j0 >> 8;
    int wjloc = (j0 & 255) + jp;
    int wunit = (wjloc >> 3) ^ (lb2 & 7);
    int woff  = ((dir * 2 + wkh) * 64 + (b0 + lb2)) * 256 + (wunit << 3) + (wjloc & 7);
    // hp reader constants
    int hkh   = jglob >> 8;
    int hjloc = jglob & 255;

    if (tid == 0) {
        MBAR_INIT(mb_h0, 1); MBAR_INIT(mb_h1, 1);
        MBAR_INIT(mb_g0, 1); MBAR_INIT(mb_g1, 1);
    }
    __syncthreads();

    // prologue: gx(0) bulk into buf 0
    if (tid == 0) {
        int t0 = dir ? (Tc - 1) : 0;
        MBAR_EXPECT(mb_g0, 6144u);
        BULK_G2S(uGX, (const void*)(gxblk + (size_t)t0 * 98304), 6144u, mb_g0);
    }
    int gxph0 = 0, gxph1 = 0;

    for (int s = 0; s < Tc; s++) {
        int rbuf = s & 1;
        int par = s & 1;
        int t = dir ? (Tc - 1 - s) : s;
        const __half* hA = g_hA[rbuf];
        __half* wA = g_hA[rbuf ^ 1];

        // tid0: poll lo half ready -> issue k-half-0 bulk; then hi half
        if (tid == 0) {
            if (s > 0) while (g_bar_gen2[ilo] - gbase_lo < s) { }
            size_t src0 = (size_t)((dir * 2 + 0) * 64 + b0) * 256;
            MBAR_EXPECT(mb_h0, 16384u);
            BULK_G2S(uH, (const void*)(hA + src0), 16384u, mb_h0);
            if (s > 0) while (g_bar_gen2[ihi] - gbase_hi < s) { }
            size_t src1 = (size_t)((dir * 2 + 1) * 64 + b0) * 256;
            MBAR_EXPECT(mb_h1, 16384u);
            BULK_G2S(uH + 16384, (const void*)(hA + src1), 16384u, mb_h1);
        }

        float acc[3][4];
#pragma unroll
        for (int i = 0; i < 3; i++)
#pragma unroll
            for (int q = 0; q < 4; q++) acc[i][q] = 0.0f;

        // ---- split-K MMA: warp group khalf_w handles its K half ----
        MBAR_WAIT(khalf_w ? mb_h1 : mb_h0, par);
        {
            uint32_t hbase = khalf_w ? 16384u : 0u;
            int kwb = khalf_w * 16;
#pragma unroll
            for (int kk = 0; kk < 16; kk++) {
                int k16 = kwb + kk;
                int unitA = kk * 2 + (a_col >> 3);
                int rowA = m_base + a_row;
                uint32_t offA = hbase + (uint32_t)(rowA * 512 + ((unitA ^ (rowA & 7)) << 4));
                uint32_t a[4];
                LDSM4(a[0], a[1], a[2], a[3], uH + offA);

                uint32_t offB = (uint32_t)(((nbase + b_row) * RPITCH + k16 * 16 + b_col) * 2);
                uint32_t bh0, bh1, bh2, bh3;
                LDSM4(bh0, bh1, bh2, bh3, uW + offB);
                MMAF16(acc[0], a, bh0, bh1);
                MMAF16(acc[1], a, bh2, bh3);

                uint32_t offB2 = (uint32_t)(((nbase + b_row2) * RPITCH + k16 * 16 + b_col) * 2);
                uint32_t ch0, ch1;
                LDSM2(ch0, ch1, uW + offB2);
                MMAF16(acc[2], a, ch0, ch1);
            }
            // dump partial gh to own buffer [gate row][batch row]
#pragma unroll
            for (int nt = 0; nt < 3; nt++) {
                int c0 = nbase + nt * 8 + (lane & 3) * 2;
                int r0 = m_base + (lane >> 2);
                sGmine[c0 * PG + r0]           = acc[nt][0];
                sGmine[(c0 + 1) * PG + r0]     = acc[nt][1];
                sGmine[c0 * PG + r0 + 8]       = acc[nt][2];
                sGmine[(c0 + 1) * PG + r0 + 8] = acc[nt][3];
            }
        }
        __syncthreads();

        // gx ready for this step?
        if (rbuf == 0) { MBAR_WAIT(mb_g0, gxph0); gxph0 ^= 1; }
        else           { MBAR_WAIT(mb_g1, gxph1); gxph1 ^= 1; }

        // gate math (partials from both K halves)
        const float* gxs = sGX + rbuf * 1536;
#pragma unroll
        for (int rep = 0; rep < 2; rep++) {
            int lb = lbase + rep * 16;
            float ghr = sG[jl * PG + lb]        + sG2[jl * PG + lb];
            float ghz = sG[(16 + jl) * PG + lb] + sG2[(16 + jl) * PG + lb];
            float ghn = sG[(32 + jl) * PG + lb] + sG2[(32 + jl) * PG + lb];
            float gr = gxs[lb * 16 + jl];
            float gz = gxs[512 + lb * 16 + jl];
            float gn = gxs[1024 + lb * 16 + jl];
            int hidx = hkh * 8192 + lb * 256 + (((hjloc >> 3) ^ (lb & 7)) << 3) + (hjloc & 7);
            float hp = __half2float(sH[hidx]);
            float rr = 1.0f / (1.0f + __expf(-(gr + ghr + br)));
            float zz = 1.0f / (1.0f + __expf(-(gz + ghz + bz)));
            float xa = gn + rr * (ghn + bn);
            float e2 = __expf(2.0f * xa);
            float nn = 1.0f - __fdividef(2.0f, e2 + 1.0f);
            sX[lb * 16 + jl] = (1.0f - zz) * nn + zz * hp;
        }
        __syncthreads();

        // h_new global write (swizzled layout): one half2 per thread
        {
            float v0 = sX[lb2 * 16 + jp];
            float v1 = sX[lb2 * 16 + jp + 1];
            __half2 h01 = {__float2half(v0), __float2half(v1)};
            *(__half2*)(wA + woff) = h01;
        }
        __syncthreads();

        // arrive at own sub-barrier (skip on last step)
        if (s != Tc - 1 && tid == 0) {
            __threadfence();
            asm volatile("fence.proxy.async;" ::: "memory");
            int old = atomicAdd(&g_bar_cnt[imine], 1);
            if (old == NHALF - 1) {
                g_bar_cnt[imine] = 0;
                __threadfence();
                g_bar_gen2[imine] = gbase_mine + s + 1;
            }
        }

        // off-critical-path: hs output (coalesced)
        {
            float2 xv = make_float2(sX[lb2 * 16 + jp], sX[lb2 * 16 + jp + 1]);
            *(float2*)&hs[((size_t)(b0 + lb2) * Tc + t) * (2 * Hc) + dir * Hc + j0 + jp] = xv;
        }
        // gx bulk prefetch for s+1
        if (s != Tc - 1 && tid == 0) {
            int tn = dir ? (Tc - 2 - s) : (s + 1);
            uint32_t mb = ((s + 1) & 1) ? mb_g1 : mb_g0;
            MBAR_EXPECT(mb, 6144u);
            BULK_G2S(uGX + ((s + 1) & 1) * 6144,
                     (const void*)(gxblk + (size_t)tn * 98304), 6144u, mb);
        }
    }

    __syncthreads();
    if (tid == 0) {
        MBAR_INVAL(mb_h0); MBAR_INVAL(mb_h1);
        MBAR_INVAL(mb_g0); MBAR_INVAL(mb_g1);
    }
}

// ---------------- copy final hidden states (de-swizzle) ----------------
__global__ void hy_copy_kernel(float* __restrict__ d_out, int layer) {
    int i = blockIdx.x * blockDim.x + threadIdx.x;   // 0..65535
    int dir = i >> 15;
    int rem = i & 32767;                              // = b*512 + j
    int b = rem >> 9;
    int j = rem & 511;
    int kh = j >> 8, jloc = j & 255;
    int off = ((dir * 2 + kh) * 64 + b) * 256 + ((((jloc >> 3) ^ (b & 7))) << 3) + (jloc & 7);
    d_out[HY_OFF + (size_t)(2 * layer + dir) * Bc * Hc + rem] =
        __half2float(g_hA[0][off]);
}

// ---------------- launch ----------------
extern "C" void kernel_launch(void* const* d_in, const int* in_sizes, int n_in,
                              void* d_out, int out_size)
{
    const float* xs    = (const float*)d_in[0];
    const float* w_ih0 = (const float*)d_in[1];
    const float* w_hh0 = (const float*)d_in[2];
    const float* b_ih0 = (const float*)d_in[3];
    const float* b_hh0 = (const float*)d_in[4];
    const float* w_ih1 = (const float*)d_in[5];
    const float* w_hh1 = (const float*)d_in[6];
    const float* b_ih1 = (const float*)d_in[7];
    const float* b_hh1 = (const float*)d_in[8];
    float* out = (float*)d_out;

    cudaFuncSetAttribute(gru_persist_mma,
                         cudaFuncAttributeMaxDynamicSharedMemorySize, PERSIST_SMEM);
    cudaFuncSetAttribute(gemm_mma,
                         cudaFuncAttributeMaxDynamicSharedMemorySize, GEMM_SMEM);

    __half *xs_hi, *xs_lo, *h0_hi, *h0_lo, *w0p, *w1p;
    cudaGetSymbolAddress((void**)&xs_hi, g_xs_hi);
    cudaGetSymbolAddress((void**)&xs_lo, g_xs_lo);
    cudaGetSymbolAddress((void**)&h0_hi, g_h0_hi);
    cudaGetSymbolAddress((void**)&h0_lo, g_h0_lo);
    cudaGetSymbolAddress((void**)&w0p, g_w0);
    cudaGetSymbolAddress((void**)&w1p, g_w1);
    float* h0out;
    cudaGetSymbolAddress((void**)&h0out, g_h0out);

    dim3 gemm_grid(Gc / 128, M_TOK / 128, 2);   // (12, 256, 2)
    dim3 persist_grid(32, 2, 2);                // 128 blocks

    size_t n_w0 = (size_t)2 * Gc * Ec;
    size_t n_w1 = (size_t)2 * Gc * 2 * Hc;
    size_t n_xs = (size_t)M_TOK * Ec;
    size_t n_h0 = (size_t)M_TOK * 2 * Hc;

    conv_fp16_kernel<<<(unsigned)((n_w0 + 255) / 256), 256>>>(w_ih0, w0p, n_w0);
    conv_fp16_kernel<<<(unsigned)((n_w1 + 255) / 256), 256>>>(w_ih1, w1p, n_w1);
    split_fp16_kernel<<<(unsigned)((n_xs + 255) / 256), 256>>>(xs, xs_hi, xs_lo, n_xs);

    // ---- layer 0 ----
    gemm_mma<<<gemm_grid, 256, GEMM_SMEM>>>(xs_hi, xs_lo, w0p, b_ih0, Ec);
    zero_h_kernel<<<(2 * 2 * Bc * 256) / 256, 256>>>();
    gru_persist_mma<<<persist_grid, 256, PERSIST_SMEM>>>(w_hh0, b_hh0, out, 0);
    hy_copy_kernel<<<(2 * Bc * Hc) / 256, 256>>>(out, 0);

    // ---- layer 1 ----
    split_fp16_kernel<<<(unsigned)((n_h0 + 255) / 256), 256>>>(h0out, h0_hi, h0_lo, n_h0);
    gemm_mma<<<gemm_grid, 256, GEMM_SMEM>>>(h0_hi, h0_lo, w1p, b_ih1, 2 * Hc);
    zero_h_kernel<<<(2 * 2 * Bc * 256) / 256, 256>>>();
    gru_persist_mma<<<persist_grid, 256, PERSIST_SMEM>>>(w_hh1, b_hh1, out, 1);
    hy_copy_kernel<<<(2 * Bc * Hc) / 256, 256>>>(out, 1);
}